// round 15
// baseline (speedup 1.0000x reference)
#include <cuda_runtime.h>
#include <cuda_bf16.h>
#include <cstdint>

#define NMAX   100000
#define EMAX   600000
#define HID    128
#define FIN    128
#define ZDIM   64
#define PKB    272    // padded bf16 row pitch (136 bf16)

// ---------------- static device scratch --------------------------------------
__device__ float g_h [(size_t)NMAX * HID];
__device__ float g_h2[(size_t)NMAX * HID];
__device__ int   g_sdeg[NMAX];
__device__ int   g_rdeg[NMAX];
__device__ int   g_offs[NMAX + 1];
__device__ int   g_cursor[NMAX];
__device__ int   g_csr[EMAX];
__device__ int   g_bsum[128];
__device__ __align__(16) uint8_t g_w0p[2][128 * PKB];
__device__ __align__(16) uint8_t g_w1p[2][128 * PKB];
__device__ __align__(16) uint8_t g_wfp[2][2][128 * PKB];

// ---------------- PTX helpers --------------------------------------------------
__device__ __forceinline__ uint32_t smem_u32(const void* p) {
    uint32_t a;
    asm("{ .reg .u64 t; cvta.to.shared.u64 t, %1; cvt.u32.u64 %0, t; }" : "=r"(a) : "l"(p));
    return a;
}
__device__ __forceinline__ void ldsm4(uint32_t* r, uint32_t addr) {
    asm volatile("ldmatrix.sync.aligned.m8n8.x4.shared.b16 {%0,%1,%2,%3}, [%4];"
                 : "=r"(r[0]), "=r"(r[1]), "=r"(r[2]), "=r"(r[3]) : "r"(addr) : "memory");
}
__device__ __forceinline__ void mma_bf16(float* c, const uint32_t* a,
                                         uint32_t b0, uint32_t b1) {
    asm volatile(
        "mma.sync.aligned.m16n8k16.row.col.f32.bf16.bf16.f32 "
        "{%0,%1,%2,%3}, {%4,%5,%6,%7}, {%8,%9}, {%0,%1,%2,%3};"
        : "+f"(c[0]), "+f"(c[1]), "+f"(c[2]), "+f"(c[3])
        : "r"(a[0]), "r"(a[1]), "r"(a[2]), "r"(a[3]), "r"(b0), "r"(b1));
}
__device__ __forceinline__ uint32_t bf2u(__nv_bfloat162 v) {
    return *reinterpret_cast<uint32_t*>(&v);
}

// ---------------- fused prep + degree-zero ---------------------------------------
__global__ void prep_zero_kernel(const float* __restrict__ W0, const float* __restrict__ W1,
                                 const float* __restrict__ Wmu, const float* __restrict__ Wls,
                                 int* sdeg, int* rdeg, int n)
{
    int idx = blockIdx.x * blockDim.x + threadIdx.x;
    if (idx < n) { sdeg[idx] = 0; rdeg[idx] = 0; }
    if (idx >= 65536) return;
    float v; uint8_t *bh, *bl; int row, col;
    if (idx < 16384) {
        int k = idx >> 7, nn = idx & 127;
        v = W0[idx]; row = nn; col = k; bh = g_w0p[0]; bl = g_w0p[1];
    } else if (idx < 32768) {
        int r = idx - 16384;
        int k = r >> 7, nn = r & 127;
        v = W1[r]; row = nn; col = k; bh = g_w1p[0]; bl = g_w1p[1];
    } else {
        int r = idx - 32768;
        int half = r >> 14, r2 = r & 16383;
        int kl = r2 >> 7, nn = r2 & 127;
        int kg = half * 128 + kl;
        v = (nn < 64) ? Wmu[kg * 64 + nn] : Wls[kg * 64 + (nn - 64)];
        row = nn; col = kl; bh = g_wfp[half][0]; bl = g_wfp[half][1];
    }
    __nv_bfloat16 h = __float2bfloat16(v);
    __nv_bfloat16 l = __float2bfloat16(v - __bfloat162float(h));
    *(__nv_bfloat16*)(bh + row * PKB + col * 2) = h;
    *(__nv_bfloat16*)(bl + row * PKB + col * 2) = l;
}

__global__ void count_deg_kernel(const int* __restrict__ snd, const int* __restrict__ rcv,
                                 int* sdeg, int* rdeg, int E) {
    int t = blockIdx.x * blockDim.x + threadIdx.x;
    if (t < E) {
        atomicAdd(&sdeg[snd[t]], 1);
        atomicAdd(&rdeg[rcv[t]], 1);
    }
}

// ---------------- multi-block scan -------------------------------------------------
__global__ __launch_bounds__(256) void scan_reduce_kernel(
    const int* __restrict__ deg, int* __restrict__ bsum, int n)
{
    __shared__ int wsum[8];
    const int tid = threadIdx.x, lane = tid & 31, warp = tid >> 5;
    int base = blockIdx.x * 2048 + tid * 8;
    int s = 0;
    if (base + 7 < n) {
        int4 a = *(const int4*)(deg + base);
        int4 b = *(const int4*)(deg + base + 4);
        s = a.x + a.y + a.z + a.w + b.x + b.y + b.z + b.w;
    } else {
        for (int q = 0; q < 8; ++q) if (base + q < n) s += deg[base + q];
    }
    #pragma unroll
    for (int o = 16; o; o >>= 1) s += __shfl_xor_sync(0xffffffffu, s, o);
    if (lane == 0) wsum[warp] = s;
    __syncthreads();
    if (tid == 0) {
        int t = 0;
        #pragma unroll
        for (int w = 0; w < 8; ++w) t += wsum[w];
        bsum[blockIdx.x] = t;
    }
}

__global__ void scan_bsums_kernel(int* bsum, int nb, int* offs, int n)
{
    int lane = threadIdx.x;
    __shared__ int carry;
    if (threadIdx.x == 0) carry = 0;
    __syncwarp();
    for (int cbase = 0; cbase < nb; cbase += 32) {
        int idx = cbase + lane;
        int vv = (idx < nb) ? bsum[idx] : 0;
        int ii = vv;
        #pragma unroll
        for (int o = 1; o < 32; o <<= 1) {
            int t = __shfl_up_sync(0xffffffffu, ii, o);
            if (lane >= o) ii += t;
        }
        int c = carry;
        if (idx < nb) bsum[idx] = c + ii - vv;
        int chunk_total = __shfl_sync(0xffffffffu, ii, 31);
        if (lane == 0) carry = c + chunk_total;
        __syncwarp();
    }
    if (lane == 0) offs[n] = carry;
}

__global__ __launch_bounds__(256) void scan_apply_kernel(
    const int* __restrict__ deg, const int* __restrict__ bexcl,
    int* __restrict__ offs, int* __restrict__ cursor, int n)
{
    __shared__ int wsum[8];
    const int tid = threadIdx.x, lane = tid & 31, warp = tid >> 5;
    int base = blockIdx.x * 2048 + tid * 8;
    int v[8];
    if (base + 7 < n) {
        int4 a = *(const int4*)(deg + base);
        int4 b = *(const int4*)(deg + base + 4);
        v[0] = a.x; v[1] = a.y; v[2] = a.z; v[3] = a.w;
        v[4] = b.x; v[5] = b.y; v[6] = b.z; v[7] = b.w;
    } else {
        #pragma unroll
        for (int q = 0; q < 8; ++q) v[q] = (base + q < n) ? deg[base + q] : 0;
    }
    int s[8]; int run = 0;
    #pragma unroll
    for (int q = 0; q < 8; ++q) { s[q] = run; run += v[q]; }
    int inc = run;
    #pragma unroll
    for (int o = 1; o < 32; o <<= 1) {
        int t = __shfl_up_sync(0xffffffffu, inc, o);
        if (lane >= o) inc += t;
    }
    if (lane == 31) wsum[warp] = inc;
    __syncthreads();
    if (warp == 0 && lane < 8) {
        int w = wsum[lane];
        int wi = w;
        #pragma unroll
        for (int o = 1; o < 8; o <<= 1) {
            int t = __shfl_up_sync(0xffu, wi, o);
            if (lane >= o) wi += t;
        }
        wsum[lane] = wi - w;
    }
    __syncthreads();
    int off = bexcl[blockIdx.x] + wsum[warp] + inc - run;
    if (base + 7 < n) {
        int4 o1 = make_int4(off + s[0], off + s[1], off + s[2], off + s[3]);
        int4 o2 = make_int4(off + s[4], off + s[5], off + s[6], off + s[7]);
        *(int4*)(offs + base) = o1;   *(int4*)(offs + base + 4) = o2;
        *(int4*)(cursor + base) = o1; *(int4*)(cursor + base + 4) = o2;
    } else {
        #pragma unroll
        for (int q = 0; q < 8; ++q)
            if (base + q < n) { offs[base + q] = off + s[q]; cursor[base + q] = off + s[q]; }
    }
}

__global__ void fill_kernel(const int* __restrict__ snd, const int* __restrict__ rcv,
                            int* cursor, int* __restrict__ csr, int E)
{
    int t = blockIdx.x * blockDim.x + threadIdx.x;
    if (t < E) {
        int r = rcv[t];
        int p = atomicAdd(&cursor[r], 1);
        csr[p] = snd[t];
    }
}

// ---------------- staging helpers ---------------------------------------------------
// 16 warps stage 64 rows (4 rows per warp), coalesced.
__device__ __forceinline__ void stage_rows4(
    const float4* __restrict__ X4, uint8_t* a_hi, uint8_t* a_lo,
    int row0, int n, int wid, int lane)
{
    #pragma unroll
    for (int rr = 0; rr < 4; ++rr) {
        int r = wid * 4 + rr;
        int i = row0 + r;
        float4 v = make_float4(0.f, 0.f, 0.f, 0.f);
        if (i < n) v = X4[(size_t)i * 32 + lane];
        __nv_bfloat162 h01 = __floats2bfloat162_rn(v.x, v.y);
        __nv_bfloat162 h23 = __floats2bfloat162_rn(v.z, v.w);
        float2 f01 = __bfloat1622float2(h01);
        float2 f23 = __bfloat1622float2(h23);
        __nv_bfloat162 l01 = __floats2bfloat162_rn(v.x - f01.x, v.y - f01.y);
        __nv_bfloat162 l23 = __floats2bfloat162_rn(v.z - f23.x, v.w - f23.y);
        uint32_t off = (uint32_t)r * PKB + lane * 8;
        *(uint2*)(a_hi + off) = make_uint2(bf2u(h01), bf2u(h23));
        *(uint2*)(a_lo + off) = make_uint2(bf2u(l01), bf2u(l23));
    }
}

// 8-rows-per-warp variant (512 threads staging 128 rows) — used by final kernel.
__device__ __forceinline__ void stage_rows_half(
    const float4* __restrict__ X4, uint8_t* a_hi, uint8_t* a_lo,
    int row0, int n, int wid, int lane)
{
    #pragma unroll 4
    for (int rr = 0; rr < 8; ++rr) {
        int r = wid * 8 + rr;
        int i = row0 + r;
        float4 v = make_float4(0.f, 0.f, 0.f, 0.f);
        if (i < n) v = X4[(size_t)i * 32 + lane];
        __nv_bfloat162 h01 = __floats2bfloat162_rn(v.x, v.y);
        __nv_bfloat162 h23 = __floats2bfloat162_rn(v.z, v.w);
        float2 f01 = __bfloat1622float2(h01);
        float2 f23 = __bfloat1622float2(h23);
        __nv_bfloat162 l01 = __floats2bfloat162_rn(v.x - f01.x, v.y - f01.y);
        __nv_bfloat162 l23 = __floats2bfloat162_rn(v.z - f23.x, v.w - f23.y);
        uint32_t off = (uint32_t)r * PKB + lane * 8;
        *(uint2*)(a_hi + off) = make_uint2(bf2u(h01), bf2u(h23));
        *(uint2*)(a_lo + off) = make_uint2(bf2u(l01), bf2u(l23));
    }
}

// CSR gather, 8 threads/row interleaved (proven round-11 version)
template <int NW, int ROWS>
__device__ __forceinline__ void stage_gather_mma(
    const float4* __restrict__ H4, const int* __restrict__ offs,
    const int* __restrict__ csr, uint8_t* a_hi, uint8_t* a_lo,
    int row0, int n, int wid, int lane)
{
    const int cseg = lane & 7;
    #pragma unroll
    for (int pass = 0; pass < ROWS / (NW * 4); ++pass) {
        int r = pass * (NW * 4) + wid * 4 + (lane >> 3);
        int i = row0 + r;
        float acc[16];
        #pragma unroll
        for (int q = 0; q < 16; ++q) acc[q] = 0.f;
        float scl = 1.f;
        if (i < n) {
            int beg = __ldg(&offs[i]), end = __ldg(&offs[i + 1]);
            if (beg < end) {
                const float4* p = H4 + (size_t)__ldg(&csr[beg]) * 32 + cseg;
                float4 c0 = __ldg(p), c1 = __ldg(p + 8), c2 = __ldg(p + 16), c3 = __ldg(p + 24);
                for (int e = beg + 1; e < end; ++e) {
                    const float4* np = H4 + (size_t)__ldg(&csr[e]) * 32 + cseg;
                    float4 n0 = __ldg(np), n1 = __ldg(np + 8),
                           n2 = __ldg(np + 16), n3 = __ldg(np + 24);
                    acc[0]  += c0.x; acc[1]  += c0.y; acc[2]  += c0.z; acc[3]  += c0.w;
                    acc[4]  += c1.x; acc[5]  += c1.y; acc[6]  += c1.z; acc[7]  += c1.w;
                    acc[8]  += c2.x; acc[9]  += c2.y; acc[10] += c2.z; acc[11] += c2.w;
                    acc[12] += c3.x; acc[13] += c3.y; acc[14] += c3.z; acc[15] += c3.w;
                    c0 = n0; c1 = n1; c2 = n2; c3 = n3;
                }
                acc[0]  += c0.x; acc[1]  += c0.y; acc[2]  += c0.z; acc[3]  += c0.w;
                acc[4]  += c1.x; acc[5]  += c1.y; acc[6]  += c1.z; acc[7]  += c1.w;
                acc[8]  += c2.x; acc[9]  += c2.y; acc[10] += c2.z; acc[11] += c2.w;
                acc[12] += c3.x; acc[13] += c3.y; acc[14] += c3.z; acc[15] += c3.w;
            }
            scl = rsqrtf(fmaxf((float)(end - beg), 1.f));
        }
        #pragma unroll
        for (int q = 0; q < 16; ++q) acc[q] *= scl;

        #pragma unroll
        for (int qq = 0; qq < 4; ++qq) {
            float x0 = acc[4 * qq], x1 = acc[4 * qq + 1];
            float x2 = acc[4 * qq + 2], x3 = acc[4 * qq + 3];
            __nv_bfloat162 h01 = __floats2bfloat162_rn(x0, x1);
            __nv_bfloat162 h23 = __floats2bfloat162_rn(x2, x3);
            float2 f01 = __bfloat1622float2(h01);
            float2 f23 = __bfloat1622float2(h23);
            __nv_bfloat162 l01 = __floats2bfloat162_rn(x0 - f01.x, x1 - f01.y);
            __nv_bfloat162 l23 = __floats2bfloat162_rn(x2 - f23.x, x3 - f23.y);
            uint32_t off = (uint32_t)r * PKB + (cseg + 8 * qq) * 8;
            *(uint2*)(a_hi + off) = make_uint2(bf2u(h01), bf2u(h23));
            *(uint2*)(a_lo + off) = make_uint2(bf2u(l01), bf2u(l23));
        }
    }
}

// ---------------- 3-term bf16 MMA, one K=128 block ----------------------------------
template <int NF16>
__device__ __forceinline__ void mma_block_t(
    float acc[2][NF16 * 2][4], uint32_t aH, uint32_t aL, uint32_t bH, uint32_t bL)
{
    #pragma unroll
    for (int k16 = 0; k16 < 8; ++k16) {
        const uint32_t kb = k16 * 32;
        uint32_t ah0[4], ah1[4], al0[4], al1[4];
        ldsm4(ah0, aH + kb);
        ldsm4(ah1, aH + 16 * PKB + kb);
        ldsm4(al0, aL + kb);
        ldsm4(al1, aL + 16 * PKB + kb);
        #pragma unroll
        for (int nf16 = 0; nf16 < NF16; ++nf16) {
            uint32_t bh[4], bl[4];
            ldsm4(bh, bH + nf16 * 16 * PKB + kb);
            ldsm4(bl, bL + nf16 * 16 * PKB + kb);
            const int nf = nf16 * 2;
            mma_bf16(acc[0][nf],     ah0, bh[0], bh[1]);
            mma_bf16(acc[0][nf],     ah0, bl[0], bl[1]);
            mma_bf16(acc[0][nf],     al0, bh[0], bh[1]);
            mma_bf16(acc[0][nf + 1], ah0, bh[2], bh[3]);
            mma_bf16(acc[0][nf + 1], ah0, bl[2], bl[3]);
            mma_bf16(acc[0][nf + 1], al0, bh[2], bh[3]);
            mma_bf16(acc[1][nf],     ah1, bh[0], bh[1]);
            mma_bf16(acc[1][nf],     ah1, bl[0], bl[1]);
            mma_bf16(acc[1][nf],     al1, bh[0], bh[1]);
            mma_bf16(acc[1][nf + 1], ah1, bh[2], bh[3]);
            mma_bf16(acc[1][nf + 1], ah1, bl[2], bl[3]);
            mma_bf16(acc[1][nf + 1], al1, bh[2], bh[3]);
        }
    }
}

// ---------------- dense GC layer: 64-row tiles, 2 CTAs/SM ----------------------------
// smem: A_hi 0 (17408), A_lo 17408, W_hi 34816, W_lo 69632,
//       bias 104448 (512B), red1 104960 (2KB: 8 chunks x 64 rows), red2 107008 (2KB)
//       -> total 109056 (2 CTAs = 213KB <= 228KB)
// 16 warps: mpos = wid&1 (m32), nquad = wid>>1 (n16 each).
#define MMA_SMEM 109056
__global__ __launch_bounds__(512, 2) void mma_dense_kernel(
    const float4* __restrict__ X4, const float4* __restrict__ Hin,
    const int* __restrict__ offs, const int* __restrict__ csr,
    const uint8_t* __restrict__ whi, const uint8_t* __restrict__ wlo,
    const float* __restrict__ bias, const int* __restrict__ sdeg,
    float* __restrict__ Hout, int n, int tiles)
{
    extern __shared__ uint8_t sm[];
    uint8_t* a_hi = sm;
    uint8_t* a_lo = sm + 17408;
    float* bias_sm = (float*)(sm + 104448);
    float* red1    = (float*)(sm + 104960);
    float* red2    = (float*)(sm + 107008);

    const int tid = threadIdx.x, wid = tid >> 5, lane = tid & 31;
    const int mpos  = wid & 1;
    const int mrow  = mpos * 32;
    const int nquad = wid >> 1;
    const int ncol  = nquad * 16;
    const int q2    = (lane & 3) * 2;

    for (int idx = tid; idx < 2176; idx += 512) {
        ((uint4*)(sm + 34816))[idx] = ((const uint4*)whi)[idx];
        ((uint4*)(sm + 69632))[idx] = ((const uint4*)wlo)[idx];
    }
    if (tid < 128) bias_sm[tid] = bias[tid];
    __syncthreads();

    float brg[4];
    #pragma unroll
    for (int nf = 0; nf < 2; ++nf) {
        brg[2 * nf]     = bias_sm[ncol + nf * 8 + q2];
        brg[2 * nf + 1] = bias_sm[ncol + nf * 8 + q2 + 1];
    }
    int rl[4];
    #pragma unroll
    for (int ri = 0; ri < 4; ++ri)
        rl[ri] = mrow + (ri >> 1) * 16 + (ri & 1) * 8 + (lane >> 2);

    const uint32_t smb  = smem_u32(sm);
    const uint32_t aoff = (lane & 15) * PKB + (lane >> 4) * 16;
    const uint32_t boff = ((lane >> 4) * 8 + (lane & 7)) * PKB + ((lane >> 3) & 1) * 16;
    const uint32_t aH = smb + mrow * PKB + aoff;
    const uint32_t aL = smb + 17408 + mrow * PKB + aoff;
    const uint32_t bH = smb + 34816 + ncol * PKB + boff;
    const uint32_t bL = smb + 69632 + ncol * PKB + boff;

    for (int t = blockIdx.x; t < tiles; t += gridDim.x) {
        const int row0 = t * 64;
        __syncthreads();
        if (csr) stage_gather_mma<16, 64>(Hin, offs, csr, a_hi, a_lo, row0, n, wid, lane);
        else     stage_rows4(X4, a_hi, a_lo, row0, n, wid, lane);
        __syncthreads();

        float acc[2][2][4];
        #pragma unroll
        for (int a = 0; a < 2; ++a)
            #pragma unroll
            for (int b = 0; b < 2; ++b)
                #pragma unroll
                for (int c = 0; c < 4; ++c) acc[a][b][c] = 0.f;

        mma_block_t<1>(acc, aH, aL, bH, bL);

        // epilogue: bias + relu + softmax(128 over 8 n-chunks) + rsqrt(sdeg)
        float rmax[4];
        #pragma unroll
        for (int ri = 0; ri < 4; ++ri) {
            const int mt = ri >> 1, h8 = (ri & 1) * 2;
            float m = -3.4e38f;
            #pragma unroll
            for (int nf = 0; nf < 2; ++nf) {
                float x0 = fmaxf(acc[mt][nf][h8]     + brg[2 * nf],     0.f);
                float x1 = fmaxf(acc[mt][nf][h8 + 1] + brg[2 * nf + 1], 0.f);
                acc[mt][nf][h8] = x0; acc[mt][nf][h8 + 1] = x1;
                m = fmaxf(m, fmaxf(x0, x1));
            }
            m = fmaxf(m, __shfl_xor_sync(0xffffffffu, m, 1));
            m = fmaxf(m, __shfl_xor_sync(0xffffffffu, m, 2));
            rmax[ri] = m;
            red1[nquad * 64 + rl[ri]] = m;
        }
        __syncthreads();
        #pragma unroll
        for (int ri = 0; ri < 4; ++ri) {
            const int mt = ri >> 1, h8 = (ri & 1) * 2;
            float m = rmax[ri];
            #pragma unroll
            for (int c = 0; c < 8; ++c) m = fmaxf(m, red1[c * 64 + rl[ri]]);
            float s = 0.f;
            #pragma unroll
            for (int nf = 0; nf < 2; ++nf) {
                float v0 = __expf(acc[mt][nf][h8] - m);
                float v1 = __expf(acc[mt][nf][h8 + 1] - m);
                acc[mt][nf][h8] = v0; acc[mt][nf][h8 + 1] = v1;
                s += v0 + v1;
            }
            s += __shfl_xor_sync(0xffffffffu, s, 1);
            s += __shfl_xor_sync(0xffffffffu, s, 2);
            red2[nquad * 64 + rl[ri]] = s;
        }
        __syncthreads();
        #pragma unroll
        for (int ri = 0; ri < 4; ++ri) {
            const int mt = ri >> 1, h8 = (ri & 1) * 2;
            const int i = row0 + rl[ri];
            if (i >= n) continue;
            float s = 0.f;
            #pragma unroll
            for (int c = 0; c < 8; ++c) s += red2[c * 64 + rl[ri]];
            float scl = rsqrtf(fmaxf((float)__ldg(&sdeg[i]), 1.f)) / s;
            float* op = Hout + (size_t)i * HID + ncol;
            #pragma unroll
            for (int nf = 0; nf < 2; ++nf)
                *(float2*)(op + nf * 8 + q2) =
                    make_float2(acc[mt][nf][h8] * scl, acc[mt][nf][h8 + 1] * scl);
        }
    }
}

// ---------------- final: 512 threads, m32xn32 warps, K=256 two-pass (unchanged) ------
#define FINAL_SMEM 209408
__global__ __launch_bounds__(512, 1) void mma_final_kernel(
    const float4* __restrict__ Hin, const int* __restrict__ offs,
    const int* __restrict__ csr, const float4* __restrict__ nodes4,
    const uint8_t* __restrict__ w0hi, const uint8_t* __restrict__ w0lo,
    const uint8_t* __restrict__ w1hi, const uint8_t* __restrict__ w1lo,
    const float* __restrict__ bmu, const float* __restrict__ bls,
    float* __restrict__ out, int n, int tiles)
{
    extern __shared__ uint8_t sm[];
    uint8_t* a_hi = sm;
    uint8_t* a_lo = sm + 34816;
    float* bias_sm = (float*)(sm + 208896);

    const int tid = threadIdx.x, wid = tid >> 5, lane = tid & 31;
    const int mrow = (wid & 3) * 32;
    const int nsub = (wid >> 2) & 1;
    const int ch   = wid >> 3;
    const int ncol = ch * 64 + nsub * 32;
    const int q2   = (lane & 3) * 2;

    for (int idx = tid; idx < 2176; idx += 512) {
        ((uint4*)(sm + 69632))[idx]  = ((const uint4*)w0hi)[idx];
        ((uint4*)(sm + 104448))[idx] = ((const uint4*)w0lo)[idx];
        ((uint4*)(sm + 139264))[idx] = ((const uint4*)w1hi)[idx];
        ((uint4*)(sm + 174080))[idx] = ((const uint4*)w1lo)[idx];
    }
    if (tid < 64) bias_sm[tid] = bmu[tid];
    else if (tid < 128) bias_sm[tid] = bls[tid - 64];
    __syncthreads();

    float brg[8];
    #pragma unroll
    for (int nf = 0; nf < 4; ++nf) {
        brg[2 * nf]     = bias_sm[ncol + nf * 8 + q2];
        brg[2 * nf + 1] = bias_sm[ncol + nf * 8 + q2 + 1];
    }
    int rl[4];
    #pragma unroll
    for (int ri = 0; ri < 4; ++ri)
        rl[ri] = mrow + (ri >> 1) * 16 + (ri & 1) * 8 + (lane >> 2);

    const uint32_t smb  = smem_u32(sm);
    const uint32_t aoff = (lane & 15) * PKB + (lane >> 4) * 16;
    const uint32_t boff = ((lane >> 4) * 8 + (lane & 7)) * PKB + ((lane >> 3) & 1) * 16;
    const uint32_t aH  = smb + mrow * PKB + aoff;
    const uint32_t aL  = smb + 34816 + mrow * PKB + aoff;
    const uint32_t b0H = smb + 69632 + ncol * PKB + boff;
    const uint32_t b0L = smb + 104448 + ncol * PKB + boff;
    const uint32_t b1H = smb + 139264 + ncol * PKB + boff;
    const uint32_t b1L = smb + 174080 + ncol * PKB + boff;

    const int cc0 = nsub * 32;

    for (int t = blockIdx.x; t < tiles; t += gridDim.x) {
        const int row0 = t * 128;

        float acc[2][4][4];
        #pragma unroll
        for (int a = 0; a < 2; ++a)
            #pragma unroll
            for (int b = 0; b < 4; ++b)
                #pragma unroll
                for (int c = 0; c < 4; ++c) acc[a][b][c] = 0.f;

        __syncthreads();
        stage_gather_mma<16, 128>(Hin, offs, csr, a_hi, a_lo, row0, n, wid, lane);
        __syncthreads();
        mma_block_t<2>(acc, aH, aL, b0H, b0L);

        __syncthreads();
        stage_rows_half(nodes4, a_hi, a_lo, row0, n, wid, lane);
        __syncthreads();
        mma_block_t<2>(acc, aH, aL, b1H, b1L);

        #pragma unroll
        for (int ri = 0; ri < 4; ++ri) {
            const int mt = ri >> 1, h8 = (ri & 1) * 2;
            const int i = row0 + rl[ri];
            if (i >= n) continue;
            float* op = out + (ch ? (size_t)n * ZDIM : 0) + (size_t)i * ZDIM + cc0;
            #pragma unroll
            for (int nf = 0; nf < 4; ++nf)
                *(float2*)(op + nf * 8 + q2) =
                    make_float2(acc[mt][nf][h8]     + brg[2 * nf],
                                acc[mt][nf][h8 + 1] + brg[2 * nf + 1]);
        }
    }
}

// ---------------- launch -------------------------------------------------------------
extern "C" void kernel_launch(void* const* d_in, const int* in_sizes, int n_in,
                              void* d_out, int out_size)
{
    const float* nodes = (const float*)d_in[0];
    const int*   snd   = (const int*)d_in[1];
    const int*   rcv   = (const int*)d_in[2];
    const float* W0    = (const float*)d_in[3];
    const float* b0    = (const float*)d_in[4];
    const float* W1    = (const float*)d_in[5];
    const float* b1    = (const float*)d_in[6];
    const float* Wmu   = (const float*)d_in[7];
    const float* bmu   = (const float*)d_in[8];
    const float* Wls   = (const float*)d_in[9];
    const float* bls   = (const float*)d_in[10];
    float* out = (float*)d_out;

    const int n = in_sizes[0] / FIN;
    const int E = in_sizes[1];

    float *h, *h2;
    int *sdeg, *rdeg, *offs, *cursor, *csr, *bsum;
    uint8_t *w0p, *w1p, *wfp;
    cudaGetSymbolAddress((void**)&h,      g_h);
    cudaGetSymbolAddress((void**)&h2,     g_h2);
    cudaGetSymbolAddress((void**)&sdeg,   g_sdeg);
    cudaGetSymbolAddress((void**)&rdeg,   g_rdeg);
    cudaGetSymbolAddress((void**)&offs,   g_offs);
    cudaGetSymbolAddress((void**)&cursor, g_cursor);
    cudaGetSymbolAddress((void**)&csr,    g_csr);
    cudaGetSymbolAddress((void**)&bsum,   g_bsum);
    cudaGetSymbolAddress((void**)&w0p,    g_w0p);
    cudaGetSymbolAddress((void**)&w1p,    g_w1p);
    cudaGetSymbolAddress((void**)&wfp,    g_wfp);

    cudaFuncSetAttribute(mma_dense_kernel, cudaFuncAttributeMaxDynamicSharedMemorySize, MMA_SMEM);
    cudaFuncSetAttribute(mma_final_kernel, cudaFuncAttributeMaxDynamicSharedMemorySize, FINAL_SMEM);

    const int tiles64  = (n + 63) / 64;
    const int tiles128 = (n + 127) / 128;
    const int IMG = 128 * PKB;
    const int pzBlocks = ((n > 65536 ? n : 65536) + 255) / 256;
    const int NB = (n + 2047) / 2048;
    const int denseGrid = tiles64 < 296 ? tiles64 : 296;

    // 0: fused prep + degree-zero
    prep_zero_kernel<<<pzBlocks, 256>>>(W0, W1, Wmu, Wls, sdeg, rdeg, n);
    // 1: degree count
    count_deg_kernel<<<(E + 255) / 256, 256>>>(snd, rcv, sdeg, rdeg, E);

    // 2-4: multi-block scan of rdeg -> offs/cursor
    scan_reduce_kernel<<<NB, 256>>>(rdeg, bsum, n);
    scan_bsums_kernel<<<1, 32>>>(bsum, NB, offs, n);
    scan_apply_kernel<<<NB, 256>>>(rdeg, bsum, offs, cursor, n);

    // 5: CSR fill
    fill_kernel<<<(E + 255) / 256, 256>>>(snd, rcv, cursor, csr, E);

    // 6: layer-1 dense (2 CTAs/SM, coalesced staging)
    mma_dense_kernel<<<denseGrid, 512, MMA_SMEM>>>(
        (const float4*)nodes, nullptr, nullptr, nullptr,
        w0p, w0p + IMG, b0, sdeg, h, n, tiles64);

    // 7: layer-2 dense (2 CTAs/SM, fused gather) — reads h, writes h2
    mma_dense_kernel<<<denseGrid, 512, MMA_SMEM>>>(
        nullptr, (const float4*)h, offs, csr,
        w1p, w1p + IMG, b1, sdeg, h2, n, tiles64);

    // 8: final heads (gather + concat)
    mma_final_kernel<<<148, 512, FINAL_SMEM>>>(
        (const float4*)h2, offs, csr, (const float4*)nodes,
        wfp, wfp + IMG, wfp + 2 * IMG, wfp + 3 * IMG,
        bmu, bls, out, n, tiles128);
}

// round 16
// speedup vs baseline: 1.0062x; 1.0062x over previous
#include <cuda_runtime.h>
#include <cuda_bf16.h>
#include <cstdint>

#define NMAX   100000
#define EMAX   600000
#define HID    128
#define FIN    128
#define ZDIM   64
#define PKB    272    // padded bf16 row pitch (136 bf16)

// ---------------- static device scratch --------------------------------------
__device__ float g_h [(size_t)NMAX * HID];
__device__ float g_h2[(size_t)NMAX * HID];
__device__ int   g_sdeg[NMAX];
__device__ int   g_rdeg[NMAX];
__device__ int   g_offs[NMAX + 1];
__device__ int   g_cursor[NMAX];
__device__ int   g_csr[EMAX];
__device__ int   g_bsum[128];
__device__ __align__(16) uint8_t g_w0p[2][128 * PKB];
__device__ __align__(16) uint8_t g_w1p[2][128 * PKB];
__device__ __align__(16) uint8_t g_wfp[2][2][128 * PKB];

// ---------------- PTX helpers --------------------------------------------------
__device__ __forceinline__ uint32_t smem_u32(const void* p) {
    uint32_t a;
    asm("{ .reg .u64 t; cvta.to.shared.u64 t, %1; cvt.u32.u64 %0, t; }" : "=r"(a) : "l"(p));
    return a;
}
__device__ __forceinline__ void ldsm4(uint32_t* r, uint32_t addr) {
    asm volatile("ldmatrix.sync.aligned.m8n8.x4.shared.b16 {%0,%1,%2,%3}, [%4];"
                 : "=r"(r[0]), "=r"(r[1]), "=r"(r[2]), "=r"(r[3]) : "r"(addr) : "memory");
}
__device__ __forceinline__ void mma_bf16(float* c, const uint32_t* a,
                                         uint32_t b0, uint32_t b1) {
    asm volatile(
        "mma.sync.aligned.m16n8k16.row.col.f32.bf16.bf16.f32 "
        "{%0,%1,%2,%3}, {%4,%5,%6,%7}, {%8,%9}, {%0,%1,%2,%3};"
        : "+f"(c[0]), "+f"(c[1]), "+f"(c[2]), "+f"(c[3])
        : "r"(a[0]), "r"(a[1]), "r"(a[2]), "r"(a[3]), "r"(b0), "r"(b1));
}
__device__ __forceinline__ uint32_t bf2u(__nv_bfloat162 v) {
    return *reinterpret_cast<uint32_t*>(&v);
}

// ---------------- fused prep + degree-zero ---------------------------------------
__global__ void prep_zero_kernel(const float* __restrict__ W0, const float* __restrict__ W1,
                                 const float* __restrict__ Wmu, const float* __restrict__ Wls,
                                 int* sdeg, int* rdeg, int n)
{
    int idx = blockIdx.x * blockDim.x + threadIdx.x;
    if (idx < n) { sdeg[idx] = 0; rdeg[idx] = 0; }
    if (idx >= 65536) return;
    float v; uint8_t *bh, *bl; int row, col;
    if (idx < 16384) {
        int k = idx >> 7, nn = idx & 127;
        v = W0[idx]; row = nn; col = k; bh = g_w0p[0]; bl = g_w0p[1];
    } else if (idx < 32768) {
        int r = idx - 16384;
        int k = r >> 7, nn = r & 127;
        v = W1[r]; row = nn; col = k; bh = g_w1p[0]; bl = g_w1p[1];
    } else {
        int r = idx - 32768;
        int half = r >> 14, r2 = r & 16383;
        int kl = r2 >> 7, nn = r2 & 127;
        int kg = half * 128 + kl;
        v = (nn < 64) ? Wmu[kg * 64 + nn] : Wls[kg * 64 + (nn - 64)];
        row = nn; col = kl; bh = g_wfp[half][0]; bl = g_wfp[half][1];
    }
    __nv_bfloat16 h = __float2bfloat16(v);
    __nv_bfloat16 l = __float2bfloat16(v - __bfloat162float(h));
    *(__nv_bfloat16*)(bh + row * PKB + col * 2) = h;
    *(__nv_bfloat16*)(bl + row * PKB + col * 2) = l;
}

__global__ void count_deg_kernel(const int* __restrict__ snd, const int* __restrict__ rcv,
                                 int* sdeg, int* rdeg, int E) {
    int t = blockIdx.x * blockDim.x + threadIdx.x;
    if (t < E) {
        atomicAdd(&sdeg[snd[t]], 1);
        atomicAdd(&rdeg[rcv[t]], 1);
    }
}

// ---------------- multi-block scan -------------------------------------------------
__global__ __launch_bounds__(256) void scan_reduce_kernel(
    const int* __restrict__ deg, int* __restrict__ bsum, int n)
{
    __shared__ int wsum[8];
    const int tid = threadIdx.x, lane = tid & 31, warp = tid >> 5;
    int base = blockIdx.x * 2048 + tid * 8;
    int s = 0;
    if (base + 7 < n) {
        int4 a = *(const int4*)(deg + base);
        int4 b = *(const int4*)(deg + base + 4);
        s = a.x + a.y + a.z + a.w + b.x + b.y + b.z + b.w;
    } else {
        for (int q = 0; q < 8; ++q) if (base + q < n) s += deg[base + q];
    }
    #pragma unroll
    for (int o = 16; o; o >>= 1) s += __shfl_xor_sync(0xffffffffu, s, o);
    if (lane == 0) wsum[warp] = s;
    __syncthreads();
    if (tid == 0) {
        int t = 0;
        #pragma unroll
        for (int w = 0; w < 8; ++w) t += wsum[w];
        bsum[blockIdx.x] = t;
    }
}

__global__ void scan_bsums_kernel(int* bsum, int nb, int* offs, int n)
{
    int lane = threadIdx.x;
    __shared__ int carry;
    if (threadIdx.x == 0) carry = 0;
    __syncwarp();
    for (int cbase = 0; cbase < nb; cbase += 32) {
        int idx = cbase + lane;
        int vv = (idx < nb) ? bsum[idx] : 0;
        int ii = vv;
        #pragma unroll
        for (int o = 1; o < 32; o <<= 1) {
            int t = __shfl_up_sync(0xffffffffu, ii, o);
            if (lane >= o) ii += t;
        }
        int c = carry;
        if (idx < nb) bsum[idx] = c + ii - vv;
        int chunk_total = __shfl_sync(0xffffffffu, ii, 31);
        if (lane == 0) carry = c + chunk_total;
        __syncwarp();
    }
    if (lane == 0) offs[n] = carry;
}

__global__ __launch_bounds__(256) void scan_apply_kernel(
    const int* __restrict__ deg, const int* __restrict__ bexcl,
    int* __restrict__ offs, int* __restrict__ cursor, int n)
{
    __shared__ int wsum[8];
    const int tid = threadIdx.x, lane = tid & 31, warp = tid >> 5;
    int base = blockIdx.x * 2048 + tid * 8;
    int v[8];
    if (base + 7 < n) {
        int4 a = *(const int4*)(deg + base);
        int4 b = *(const int4*)(deg + base + 4);
        v[0] = a.x; v[1] = a.y; v[2] = a.z; v[3] = a.w;
        v[4] = b.x; v[5] = b.y; v[6] = b.z; v[7] = b.w;
    } else {
        #pragma unroll
        for (int q = 0; q < 8; ++q) v[q] = (base + q < n) ? deg[base + q] : 0;
    }
    int s[8]; int run = 0;
    #pragma unroll
    for (int q = 0; q < 8; ++q) { s[q] = run; run += v[q]; }
    int inc = run;
    #pragma unroll
    for (int o = 1; o < 32; o <<= 1) {
        int t = __shfl_up_sync(0xffffffffu, inc, o);
        if (lane >= o) inc += t;
    }
    if (lane == 31) wsum[warp] = inc;
    __syncthreads();
    if (warp == 0 && lane < 8) {
        int w = wsum[lane];
        int wi = w;
        #pragma unroll
        for (int o = 1; o < 8; o <<= 1) {
            int t = __shfl_up_sync(0xffu, wi, o);
            if (lane >= o) wi += t;
        }
        wsum[lane] = wi - w;
    }
    __syncthreads();
    int off = bexcl[blockIdx.x] + wsum[warp] + inc - run;
    if (base + 7 < n) {
        int4 o1 = make_int4(off + s[0], off + s[1], off + s[2], off + s[3]);
        int4 o2 = make_int4(off + s[4], off + s[5], off + s[6], off + s[7]);
        *(int4*)(offs + base) = o1;   *(int4*)(offs + base + 4) = o2;
        *(int4*)(cursor + base) = o1; *(int4*)(cursor + base + 4) = o2;
    } else {
        #pragma unroll
        for (int q = 0; q < 8; ++q)
            if (base + q < n) { offs[base + q] = off + s[q]; cursor[base + q] = off + s[q]; }
    }
}

__global__ void fill_kernel(const int* __restrict__ snd, const int* __restrict__ rcv,
                            int* cursor, int* __restrict__ csr, int E)
{
    int t = blockIdx.x * blockDim.x + threadIdx.x;
    if (t < E) {
        int r = rcv[t];
        int p = atomicAdd(&cursor[r], 1);
        csr[p] = snd[t];
    }
}

// ---------------- staging: coalesced rows (NW warps stage NW*16 rows) ---------------
template <int NW>
__device__ __forceinline__ void stage_rows_mma(
    const float4* __restrict__ X4, uint8_t* a_hi, uint8_t* a_lo,
    int row0, int n, int wid, int lane)
{
    #pragma unroll 4
    for (int rr = 0; rr < 16; ++rr) {
        int r = wid * 16 + rr;
        int i = row0 + r;
        float4 v = make_float4(0.f, 0.f, 0.f, 0.f);
        if (i < n) v = X4[(size_t)i * 32 + lane];
        __nv_bfloat162 h01 = __floats2bfloat162_rn(v.x, v.y);
        __nv_bfloat162 h23 = __floats2bfloat162_rn(v.z, v.w);
        float2 f01 = __bfloat1622float2(h01);
        float2 f23 = __bfloat1622float2(h23);
        __nv_bfloat162 l01 = __floats2bfloat162_rn(v.x - f01.x, v.y - f01.y);
        __nv_bfloat162 l23 = __floats2bfloat162_rn(v.z - f23.x, v.w - f23.y);
        uint32_t off = (uint32_t)r * PKB + lane * 8;
        *(uint2*)(a_hi + off) = make_uint2(bf2u(h01), bf2u(h23));
        *(uint2*)(a_lo + off) = make_uint2(bf2u(l01), bf2u(l23));
    }
}

// 8-rows-per-warp variant (512 threads staging only 128 rows).
__device__ __forceinline__ void stage_rows_half(
    const float4* __restrict__ X4, uint8_t* a_hi, uint8_t* a_lo,
    int row0, int n, int wid, int lane)
{
    #pragma unroll 4
    for (int rr = 0; rr < 8; ++rr) {
        int r = wid * 8 + rr;
        int i = row0 + r;
        float4 v = make_float4(0.f, 0.f, 0.f, 0.f);
        if (i < n) v = X4[(size_t)i * 32 + lane];
        __nv_bfloat162 h01 = __floats2bfloat162_rn(v.x, v.y);
        __nv_bfloat162 h23 = __floats2bfloat162_rn(v.z, v.w);
        float2 f01 = __bfloat1622float2(h01);
        float2 f23 = __bfloat1622float2(h23);
        __nv_bfloat162 l01 = __floats2bfloat162_rn(v.x - f01.x, v.y - f01.y);
        __nv_bfloat162 l23 = __floats2bfloat162_rn(v.z - f23.x, v.w - f23.y);
        uint32_t off = (uint32_t)r * PKB + lane * 8;
        *(uint2*)(a_hi + off) = make_uint2(bf2u(h01), bf2u(h23));
        *(uint2*)(a_lo + off) = make_uint2(bf2u(l01), bf2u(l23));
    }
}

// ---------------- staging: CSR gather, 8 threads/row, interleaved loads -------------
template <int NW, int ROWS>
__device__ __forceinline__ void stage_gather_mma(
    const float4* __restrict__ H4, const int* __restrict__ offs,
    const int* __restrict__ csr, uint8_t* a_hi, uint8_t* a_lo,
    int row0, int n, int wid, int lane)
{
    const int cseg = lane & 7;
    #pragma unroll
    for (int pass = 0; pass < ROWS / (NW * 4); ++pass) {
        int r = pass * (NW * 4) + wid * 4 + (lane >> 3);
        int i = row0 + r;
        float acc[16];
        #pragma unroll
        for (int q = 0; q < 16; ++q) acc[q] = 0.f;
        float scl = 1.f;
        if (i < n) {
            int beg = __ldg(&offs[i]), end = __ldg(&offs[i + 1]);
            if (beg < end) {
                const float4* p = H4 + (size_t)__ldg(&csr[beg]) * 32 + cseg;
                float4 c0 = __ldg(p), c1 = __ldg(p + 8), c2 = __ldg(p + 16), c3 = __ldg(p + 24);
                for (int e = beg + 1; e < end; ++e) {
                    const float4* np = H4 + (size_t)__ldg(&csr[e]) * 32 + cseg;
                    float4 n0 = __ldg(np), n1 = __ldg(np + 8),
                           n2 = __ldg(np + 16), n3 = __ldg(np + 24);
                    acc[0]  += c0.x; acc[1]  += c0.y; acc[2]  += c0.z; acc[3]  += c0.w;
                    acc[4]  += c1.x; acc[5]  += c1.y; acc[6]  += c1.z; acc[7]  += c1.w;
                    acc[8]  += c2.x; acc[9]  += c2.y; acc[10] += c2.z; acc[11] += c2.w;
                    acc[12] += c3.x; acc[13] += c3.y; acc[14] += c3.z; acc[15] += c3.w;
                    c0 = n0; c1 = n1; c2 = n2; c3 = n3;
                }
                acc[0]  += c0.x; acc[1]  += c0.y; acc[2]  += c0.z; acc[3]  += c0.w;
                acc[4]  += c1.x; acc[5]  += c1.y; acc[6]  += c1.z; acc[7]  += c1.w;
                acc[8]  += c2.x; acc[9]  += c2.y; acc[10] += c2.z; acc[11] += c2.w;
                acc[12] += c3.x; acc[13] += c3.y; acc[14] += c3.z; acc[15] += c3.w;
            }
            scl = rsqrtf(fmaxf((float)(end - beg), 1.f));
        }
        #pragma unroll
        for (int q = 0; q < 16; ++q) acc[q] *= scl;

        #pragma unroll
        for (int qq = 0; qq < 4; ++qq) {
            float x0 = acc[4 * qq], x1 = acc[4 * qq + 1];
            float x2 = acc[4 * qq + 2], x3 = acc[4 * qq + 3];
            __nv_bfloat162 h01 = __floats2bfloat162_rn(x0, x1);
            __nv_bfloat162 h23 = __floats2bfloat162_rn(x2, x3);
            float2 f01 = __bfloat1622float2(h01);
            float2 f23 = __bfloat1622float2(h23);
            __nv_bfloat162 l01 = __floats2bfloat162_rn(x0 - f01.x, x1 - f01.y);
            __nv_bfloat162 l23 = __floats2bfloat162_rn(x2 - f23.x, x3 - f23.y);
            uint32_t off = (uint32_t)r * PKB + (cseg + 8 * qq) * 8;
            *(uint2*)(a_hi + off) = make_uint2(bf2u(h01), bf2u(h23));
            *(uint2*)(a_lo + off) = make_uint2(bf2u(l01), bf2u(l23));
        }
    }
}

// ---------------- 3-term bf16 MMA, one K=128 block, m32 x (NF16*16) per warp ---------
template <int NF16>
__device__ __forceinline__ void mma_block_t(
    float acc[2][NF16 * 2][4], uint32_t aH, uint32_t aL, uint32_t bH, uint32_t bL)
{
    #pragma unroll
    for (int k16 = 0; k16 < 8; ++k16) {
        const uint32_t kb = k16 * 32;
        uint32_t ah0[4], ah1[4], al0[4], al1[4];
        ldsm4(ah0, aH + kb);
        ldsm4(ah1, aH + 16 * PKB + kb);
        ldsm4(al0, aL + kb);
        ldsm4(al1, aL + 16 * PKB + kb);
        #pragma unroll
        for (int nf16 = 0; nf16 < NF16; ++nf16) {
            uint32_t bh[4], bl[4];
            ldsm4(bh, bH + nf16 * 16 * PKB + kb);
            ldsm4(bl, bL + nf16 * 16 * PKB + kb);
            const int nf = nf16 * 2;
            mma_bf16(acc[0][nf],     ah0, bh[0], bh[1]);
            mma_bf16(acc[0][nf],     ah0, bl[0], bl[1]);
            mma_bf16(acc[0][nf],     al0, bh[0], bh[1]);
            mma_bf16(acc[0][nf + 1], ah0, bh[2], bh[3]);
            mma_bf16(acc[0][nf + 1], ah0, bl[2], bl[3]);
            mma_bf16(acc[0][nf + 1], al0, bh[2], bh[3]);
            mma_bf16(acc[1][nf],     ah1, bh[0], bh[1]);
            mma_bf16(acc[1][nf],     ah1, bl[0], bl[1]);
            mma_bf16(acc[1][nf],     al1, bh[0], bh[1]);
            mma_bf16(acc[1][nf + 1], ah1, bh[2], bh[3]);
            mma_bf16(acc[1][nf + 1], ah1, bl[2], bl[3]);
            mma_bf16(acc[1][nf + 1], al1, bh[2], bh[3]);
        }
    }
}

// ---------------- dense GC layer: 512 threads, 256-row tiles ------------------------
#define MMA_SMEM 213504
__global__ __launch_bounds__(512, 1) void mma_dense_kernel(
    const float4* __restrict__ X4, const float4* __restrict__ Hin,
    const int* __restrict__ offs, const int* __restrict__ csr,
    const uint8_t* __restrict__ whi, const uint8_t* __restrict__ wlo,
    const float* __restrict__ bias, const int* __restrict__ sdeg,
    float* __restrict__ Hout, int n, int tiles)
{
    extern __shared__ uint8_t sm[];
    uint8_t* a_hi = sm;
    uint8_t* a_lo = sm + 69632;
    float* bias_sm = (float*)(sm + 208896);
    float* red1    = (float*)(sm + 209408);
    float* red2    = (float*)(sm + 211456);

    const int tid = threadIdx.x, wid = tid >> 5, lane = tid & 31;
    const int sub  = wid >> 3;
    const int mrow = (wid & 3) * 32 + sub * 128;
    const int ch   = (wid >> 2) & 1;
    const int ncol = ch * 64;
    const int q2   = (lane & 3) * 2;

    for (int idx = tid; idx < 2176; idx += 512) {
        ((uint4*)(sm + 139264))[idx] = ((const uint4*)whi)[idx];
        ((uint4*)(sm + 174080))[idx] = ((const uint4*)wlo)[idx];
    }
    if (tid < 128) bias_sm[tid] = bias[tid];
    __syncthreads();

    float brg[16];
    #pragma unroll
    for (int nf = 0; nf < 8; ++nf) {
        brg[2 * nf]     = bias_sm[ncol + nf * 8 + q2];
        brg[2 * nf + 1] = bias_sm[ncol + nf * 8 + q2 + 1];
    }
    int rl[4];
    #pragma unroll
    for (int ri = 0; ri < 4; ++ri)
        rl[ri] = mrow + (ri >> 1) * 16 + (ri & 1) * 8 + (lane >> 2);

    const uint32_t smb  = smem_u32(sm);
    const uint32_t aoff = (lane & 15) * PKB + (lane >> 4) * 16;
    const uint32_t boff = ((lane >> 4) * 8 + (lane & 7)) * PKB + ((lane >> 3) & 1) * 16;
    const uint32_t aH = smb + mrow * PKB + aoff;
    const uint32_t aL = smb + 69632 + mrow * PKB + aoff;
    const uint32_t bH = smb + 139264 + ncol * PKB + boff;
    const uint32_t bL = smb + 174080 + ncol * PKB + boff;

    for (int t = blockIdx.x; t < tiles; t += gridDim.x) {
        const int row0 = t * 256;
        __syncthreads();
        if (csr) stage_gather_mma<16, 256>(Hin, offs, csr, a_hi, a_lo, row0, n, wid, lane);
        else     stage_rows_mma<16>(X4, a_hi, a_lo, row0, n, wid, lane);
        __syncthreads();

        float acc[2][8][4];
        #pragma unroll
        for (int a = 0; a < 2; ++a)
            #pragma unroll
            for (int b = 0; b < 8; ++b)
                #pragma unroll
                for (int c = 0; c < 4; ++c) acc[a][b][c] = 0.f;

        mma_block_t<4>(acc, aH, aL, bH, bL);

        float rmax[4];
        #pragma unroll
        for (int ri = 0; ri < 4; ++ri) {
            const int mt = ri >> 1, h8 = (ri & 1) * 2;
            float m = -3.4e38f;
            #pragma unroll
            for (int nf = 0; nf < 8; ++nf) {
                float x0 = fmaxf(acc[mt][nf][h8]     + brg[2 * nf],     0.f);
                float x1 = fmaxf(acc[mt][nf][h8 + 1] + brg[2 * nf + 1], 0.f);
                acc[mt][nf][h8] = x0; acc[mt][nf][h8 + 1] = x1;
                m = fmaxf(m, fmaxf(x0, x1));
            }
            m = fmaxf(m, __shfl_xor_sync(0xffffffffu, m, 1));
            m = fmaxf(m, __shfl_xor_sync(0xffffffffu, m, 2));
            rmax[ri] = m;
            red1[ch * 256 + rl[ri]] = m;
        }
        __syncthreads();
        #pragma unroll
        for (int ri = 0; ri < 4; ++ri) {
            const int mt = ri >> 1, h8 = (ri & 1) * 2;
            float m = fmaxf(rmax[ri], red1[(ch ^ 1) * 256 + rl[ri]]);
            float s = 0.f;
            #pragma unroll
            for (int nf = 0; nf < 8; ++nf) {
                float v0 = __expf(acc[mt][nf][h8] - m);
                float v1 = __expf(acc[mt][nf][h8 + 1] - m);
                acc[mt][nf][h8] = v0; acc[mt][nf][h8 + 1] = v1;
                s += v0 + v1;
            }
            s += __shfl_xor_sync(0xffffffffu, s, 1);
            s += __shfl_xor_sync(0xffffffffu, s, 2);
            red2[ch * 256 + rl[ri]] = s;
        }
        __syncthreads();
        #pragma unroll
        for (int ri = 0; ri < 4; ++ri) {
            const int mt = ri >> 1, h8 = (ri & 1) * 2;
            const int i = row0 + rl[ri];
            if (i >= n) continue;
            float s = red2[rl[ri]] + red2[256 + rl[ri]];
            float scl = rsqrtf(fmaxf((float)__ldg(&sdeg[i]), 1.f)) / s;
            float* op = Hout + (size_t)i * HID + ncol;
            #pragma unroll
            for (int nf = 0; nf < 8; ++nf)
                *(float2*)(op + nf * 8 + q2) =
                    make_float2(acc[mt][nf][h8] * scl, acc[mt][nf][h8 + 1] * scl);
        }
    }
}

// ---------------- final: 512 threads, m32xn32 warps, K=256 two-pass ------------------
#define FINAL_SMEM 209408
__global__ __launch_bounds__(512, 1) void mma_final_kernel(
    const float4* __restrict__ Hin, const int* __restrict__ offs,
    const int* __restrict__ csr, const float4* __restrict__ nodes4,
    const uint8_t* __restrict__ w0hi, const uint8_t* __restrict__ w0lo,
    const uint8_t* __restrict__ w1hi, const uint8_t* __restrict__ w1lo,
    const float* __restrict__ bmu, const float* __restrict__ bls,
    float* __restrict__ out, int n, int tiles)
{
    extern __shared__ uint8_t sm[];
    uint8_t* a_hi = sm;
    uint8_t* a_lo = sm + 34816;
    float* bias_sm = (float*)(sm + 208896);

    const int tid = threadIdx.x, wid = tid >> 5, lane = tid & 31;
    const int mrow = (wid & 3) * 32;
    const int nsub = (wid >> 2) & 1;
    const int ch   = wid >> 3;
    const int ncol = ch * 64 + nsub * 32;
    const int q2   = (lane & 3) * 2;

    for (int idx = tid; idx < 2176; idx += 512) {
        ((uint4*)(sm + 69632))[idx]  = ((const uint4*)w0hi)[idx];
        ((uint4*)(sm + 104448))[idx] = ((const uint4*)w0lo)[idx];
        ((uint4*)(sm + 139264))[idx] = ((const uint4*)w1hi)[idx];
        ((uint4*)(sm + 174080))[idx] = ((const uint4*)w1lo)[idx];
    }
    if (tid < 64) bias_sm[tid] = bmu[tid];
    else if (tid < 128) bias_sm[tid] = bls[tid - 64];
    __syncthreads();

    float brg[8];
    #pragma unroll
    for (int nf = 0; nf < 4; ++nf) {
        brg[2 * nf]     = bias_sm[ncol + nf * 8 + q2];
        brg[2 * nf + 1] = bias_sm[ncol + nf * 8 + q2 + 1];
    }
    int rl[4];
    #pragma unroll
    for (int ri = 0; ri < 4; ++ri)
        rl[ri] = mrow + (ri >> 1) * 16 + (ri & 1) * 8 + (lane >> 2);

    const uint32_t smb  = smem_u32(sm);
    const uint32_t aoff = (lane & 15) * PKB + (lane >> 4) * 16;
    const uint32_t boff = ((lane >> 4) * 8 + (lane & 7)) * PKB + ((lane >> 3) & 1) * 16;
    const uint32_t aH  = smb + mrow * PKB + aoff;
    const uint32_t aL  = smb + 34816 + mrow * PKB + aoff;
    const uint32_t b0H = smb + 69632 + ncol * PKB + boff;
    const uint32_t b0L = smb + 104448 + ncol * PKB + boff;
    const uint32_t b1H = smb + 139264 + ncol * PKB + boff;
    const uint32_t b1L = smb + 174080 + ncol * PKB + boff;

    const int cc0 = nsub * 32;

    for (int t = blockIdx.x; t < tiles; t += gridDim.x) {
        const int row0 = t * 128;

        float acc[2][4][4];
        #pragma unroll
        for (int a = 0; a < 2; ++a)
            #pragma unroll
            for (int b = 0; b < 4; ++b)
                #pragma unroll
                for (int c = 0; c < 4; ++c) acc[a][b][c] = 0.f;

        __syncthreads();
        stage_gather_mma<16, 128>(Hin, offs, csr, a_hi, a_lo, row0, n, wid, lane);
        __syncthreads();
        mma_block_t<2>(acc, aH, aL, b0H, b0L);

        __syncthreads();
        stage_rows_half(nodes4, a_hi, a_lo, row0, n, wid, lane);
        __syncthreads();
        mma_block_t<2>(acc, aH, aL, b1H, b1L);

        #pragma unroll
        for (int ri = 0; ri < 4; ++ri) {
            const int mt = ri >> 1, h8 = (ri & 1) * 2;
            const int i = row0 + rl[ri];
            if (i >= n) continue;
            float* op = out + (ch ? (size_t)n * ZDIM : 0) + (size_t)i * ZDIM + cc0;
            #pragma unroll
            for (int nf = 0; nf < 4; ++nf)
                *(float2*)(op + nf * 8 + q2) =
                    make_float2(acc[mt][nf][h8]     + brg[2 * nf],
                                acc[mt][nf][h8 + 1] + brg[2 * nf + 1]);
        }
    }
}

// ---------------- launch -------------------------------------------------------------
extern "C" void kernel_launch(void* const* d_in, const int* in_sizes, int n_in,
                              void* d_out, int out_size)
{
    const float* nodes = (const float*)d_in[0];
    const int*   snd   = (const int*)d_in[1];
    const int*   rcv   = (const int*)d_in[2];
    const float* W0    = (const float*)d_in[3];
    const float* b0    = (const float*)d_in[4];
    const float* W1    = (const float*)d_in[5];
    const float* b1    = (const float*)d_in[6];
    const float* Wmu   = (const float*)d_in[7];
    const float* bmu   = (const float*)d_in[8];
    const float* Wls   = (const float*)d_in[9];
    const float* bls   = (const float*)d_in[10];
    float* out = (float*)d_out;

    const int n = in_sizes[0] / FIN;
    const int E = in_sizes[1];

    float *h, *h2;
    int *sdeg, *rdeg, *offs, *cursor, *csr, *bsum;
    uint8_t *w0p, *w1p, *wfp;
    cudaGetSymbolAddress((void**)&h,      g_h);
    cudaGetSymbolAddress((void**)&h2,     g_h2);
    cudaGetSymbolAddress((void**)&sdeg,   g_sdeg);
    cudaGetSymbolAddress((void**)&rdeg,   g_rdeg);
    cudaGetSymbolAddress((void**)&offs,   g_offs);
    cudaGetSymbolAddress((void**)&cursor, g_cursor);
    cudaGetSymbolAddress((void**)&csr,    g_csr);
    cudaGetSymbolAddress((void**)&bsum,   g_bsum);
    cudaGetSymbolAddress((void**)&w0p,    g_w0p);
    cudaGetSymbolAddress((void**)&w1p,    g_w1p);
    cudaGetSymbolAddress((void**)&wfp,    g_wfp);

    cudaFuncSetAttribute(mma_dense_kernel, cudaFuncAttributeMaxDynamicSharedMemorySize, MMA_SMEM);
    cudaFuncSetAttribute(mma_final_kernel, cudaFuncAttributeMaxDynamicSharedMemorySize, FINAL_SMEM);

    const int tiles256 = (n + 255) / 256;
    const int tiles128 = (n + 127) / 128;
    const int IMG = 128 * PKB;
    const int pzBlocks = ((n > 65536 ? n : 65536) + 255) / 256;
    const int NB = (n + 2047) / 2048;
    const int denseGrid = tiles256 < 296 ? tiles256 : 296;
    const int finalGrid = tiles128 < 296 ? tiles128 : 296;

    // 0: fused prep + degree-zero
    prep_zero_kernel<<<pzBlocks, 256>>>(W0, W1, Wmu, Wls, sdeg, rdeg, n);
    // 1: degree count
    count_deg_kernel<<<(E + 255) / 256, 256>>>(snd, rcv, sdeg, rdeg, E);

    // 2-4: multi-block scan of rdeg -> offs/cursor
    scan_reduce_kernel<<<NB, 256>>>(rdeg, bsum, n);
    scan_bsums_kernel<<<1, 32>>>(bsum, NB, offs, n);
    scan_apply_kernel<<<NB, 256>>>(rdeg, bsum, offs, cursor, n);

    // 5: CSR fill
    fill_kernel<<<(E + 255) / 256, 256>>>(snd, rcv, cursor, csr, E);

    // 6: layer-1 dense (coalesced staging)
    mma_dense_kernel<<<denseGrid, 512, MMA_SMEM>>>(
        (const float4*)nodes, nullptr, nullptr, nullptr,
        w0p, w0p + IMG, b0, sdeg, h, n, tiles256);

    // 7: layer-2 dense (interleaved 8-thread/row gather) — reads h, writes h2
    mma_dense_kernel<<<denseGrid, 512, MMA_SMEM>>>(
        nullptr, (const float4*)h, offs, csr,
        w1p, w1p + IMG, b1, sdeg, h2, n, tiles256);

    // 8: final heads (gather + concat)
    mma_final_kernel<<<finalGrid, 512, FINAL_SMEM>>>(
        (const float4*)h2, offs, csr, (const float4*)nodes,
        wfp, wfp + IMG, wfp + 2 * IMG, wfp + 3 * IMG,
        bmu, bls, out, n, tiles128);
}

// round 17
// speedup vs baseline: 1.0162x; 1.0099x over previous
#include <cuda_runtime.h>
#include <cuda_bf16.h>
#include <cstdint>

#define NMAX   100000
#define EMAX   600000
#define HID    128
#define FIN    128
#define ZDIM   64
#define PKB    272    // padded bf16 row pitch (136 bf16)

// ---------------- static device scratch --------------------------------------
__device__ float g_h [(size_t)NMAX * HID];
__device__ float g_h2[(size_t)NMAX * HID];
__device__ int   g_sdeg[NMAX];
__device__ int   g_rdeg[NMAX];
__device__ int   g_offs[NMAX + 1];
__device__ int   g_cursor[NMAX];
__device__ int   g_csr[EMAX];
__device__ int   g_bsum[128];
__device__ __align__(16) uint8_t g_w0p[2][128 * PKB];
__device__ __align__(16) uint8_t g_w1p[2][128 * PKB];
__device__ __align__(16) uint8_t g_wfp[2][2][128 * PKB];

// ---------------- PTX helpers --------------------------------------------------
__device__ __forceinline__ uint32_t smem_u32(const void* p) {
    uint32_t a;
    asm("{ .reg .u64 t; cvta.to.shared.u64 t, %1; cvt.u32.u64 %0, t; }" : "=r"(a) : "l"(p));
    return a;
}
__device__ __forceinline__ void ldsm4(uint32_t* r, uint32_t addr) {
    asm volatile("ldmatrix.sync.aligned.m8n8.x4.shared.b16 {%0,%1,%2,%3}, [%4];"
                 : "=r"(r[0]), "=r"(r[1]), "=r"(r[2]), "=r"(r[3]) : "r"(addr) : "memory");
}
__device__ __forceinline__ void mma_bf16(float* c, const uint32_t* a,
                                         uint32_t b0, uint32_t b1) {
    asm volatile(
        "mma.sync.aligned.m16n8k16.row.col.f32.bf16.bf16.f32 "
        "{%0,%1,%2,%3}, {%4,%5,%6,%7}, {%8,%9}, {%0,%1,%2,%3};"
        : "+f"(c[0]), "+f"(c[1]), "+f"(c[2]), "+f"(c[3])
        : "r"(a[0]), "r"(a[1]), "r"(a[2]), "r"(a[3]), "r"(b0), "r"(b1));
}
__device__ __forceinline__ uint32_t bf2u(__nv_bfloat162 v) {
    return *reinterpret_cast<uint32_t*>(&v);
}

// ---------------- fused prep + degree-zero ---------------------------------------
__global__ void prep_zero_kernel(const float* __restrict__ W0, const float* __restrict__ W1,
                                 const float* __restrict__ Wmu, const float* __restrict__ Wls,
                                 int* sdeg, int* rdeg, int n)
{
    int idx = blockIdx.x * blockDim.x + threadIdx.x;
    if (idx < n) { sdeg[idx] = 0; rdeg[idx] = 0; }
    if (idx >= 65536) return;
    float v; uint8_t *bh, *bl; int row, col;
    if (idx < 16384) {
        int k = idx >> 7, nn = idx & 127;
        v = W0[idx]; row = nn; col = k; bh = g_w0p[0]; bl = g_w0p[1];
    } else if (idx < 32768) {
        int r = idx - 16384;
        int k = r >> 7, nn = r & 127;
        v = W1[r]; row = nn; col = k; bh = g_w1p[0]; bl = g_w1p[1];
    } else {
        int r = idx - 32768;
        int half = r >> 14, r2 = r & 16383;
        int kl = r2 >> 7, nn = r2 & 127;
        int kg = half * 128 + kl;
        v = (nn < 64) ? Wmu[kg * 64 + nn] : Wls[kg * 64 + (nn - 64)];
        row = nn; col = kl; bh = g_wfp[half][0]; bl = g_wfp[half][1];
    }
    __nv_bfloat16 h = __float2bfloat16(v);
    __nv_bfloat16 l = __float2bfloat16(v - __bfloat162float(h));
    *(__nv_bfloat16*)(bh + row * PKB + col * 2) = h;
    *(__nv_bfloat16*)(bl + row * PKB + col * 2) = l;
}

__global__ void count_deg_kernel(const int* __restrict__ snd, const int* __restrict__ rcv,
                                 int* sdeg, int* rdeg, int E) {
    int t = blockIdx.x * blockDim.x + threadIdx.x;
    if (t < E) {
        atomicAdd(&sdeg[snd[t]], 1);
        atomicAdd(&rdeg[rcv[t]], 1);
    }
}

// ---------------- multi-block scan -------------------------------------------------
__global__ __launch_bounds__(256) void scan_reduce_kernel(
    const int* __restrict__ deg, int* __restrict__ bsum, int n)
{
    __shared__ int wsum[8];
    const int tid = threadIdx.x, lane = tid & 31, warp = tid >> 5;
    int base = blockIdx.x * 2048 + tid * 8;
    int s = 0;
    if (base + 7 < n) {
        int4 a = *(const int4*)(deg + base);
        int4 b = *(const int4*)(deg + base + 4);
        s = a.x + a.y + a.z + a.w + b.x + b.y + b.z + b.w;
    } else {
        for (int q = 0; q < 8; ++q) if (base + q < n) s += deg[base + q];
    }
    #pragma unroll
    for (int o = 16; o; o >>= 1) s += __shfl_xor_sync(0xffffffffu, s, o);
    if (lane == 0) wsum[warp] = s;
    __syncthreads();
    if (tid == 0) {
        int t = 0;
        #pragma unroll
        for (int w = 0; w < 8; ++w) t += wsum[w];
        bsum[blockIdx.x] = t;
    }
}

__global__ void scan_bsums_kernel(int* bsum, int nb, int* offs, int n)
{
    int lane = threadIdx.x;
    __shared__ int carry;
    if (threadIdx.x == 0) carry = 0;
    __syncwarp();
    for (int cbase = 0; cbase < nb; cbase += 32) {
        int idx = cbase + lane;
        int vv = (idx < nb) ? bsum[idx] : 0;
        int ii = vv;
        #pragma unroll
        for (int o = 1; o < 32; o <<= 1) {
            int t = __shfl_up_sync(0xffffffffu, ii, o);
            if (lane >= o) ii += t;
        }
        int c = carry;
        if (idx < nb) bsum[idx] = c + ii - vv;
        int chunk_total = __shfl_sync(0xffffffffu, ii, 31);
        if (lane == 0) carry = c + chunk_total;
        __syncwarp();
    }
    if (lane == 0) offs[n] = carry;
}

__global__ __launch_bounds__(256) void scan_apply_kernel(
    const int* __restrict__ deg, const int* __restrict__ bexcl,
    int* __restrict__ offs, int* __restrict__ cursor, int n)
{
    __shared__ int wsum[8];
    const int tid = threadIdx.x, lane = tid & 31, warp = tid >> 5;
    int base = blockIdx.x * 2048 + tid * 8;
    int v[8];
    if (base + 7 < n) {
        int4 a = *(const int4*)(deg + base);
        int4 b = *(const int4*)(deg + base + 4);
        v[0] = a.x; v[1] = a.y; v[2] = a.z; v[3] = a.w;
        v[4] = b.x; v[5] = b.y; v[6] = b.z; v[7] = b.w;
    } else {
        #pragma unroll
        for (int q = 0; q < 8; ++q) v[q] = (base + q < n) ? deg[base + q] : 0;
    }
    int s[8]; int run = 0;
    #pragma unroll
    for (int q = 0; q < 8; ++q) { s[q] = run; run += v[q]; }
    int inc = run;
    #pragma unroll
    for (int o = 1; o < 32; o <<= 1) {
        int t = __shfl_up_sync(0xffffffffu, inc, o);
        if (lane >= o) inc += t;
    }
    if (lane == 31) wsum[warp] = inc;
    __syncthreads();
    if (warp == 0 && lane < 8) {
        int w = wsum[lane];
        int wi = w;
        #pragma unroll
        for (int o = 1; o < 8; o <<= 1) {
            int t = __shfl_up_sync(0xffu, wi, o);
            if (lane >= o) wi += t;
        }
        wsum[lane] = wi - w;
    }
    __syncthreads();
    int off = bexcl[blockIdx.x] + wsum[warp] + inc - run;
    if (base + 7 < n) {
        int4 o1 = make_int4(off + s[0], off + s[1], off + s[2], off + s[3]);
        int4 o2 = make_int4(off + s[4], off + s[5], off + s[6], off + s[7]);
        *(int4*)(offs + base) = o1;   *(int4*)(offs + base + 4) = o2;
        *(int4*)(cursor + base) = o1; *(int4*)(cursor + base + 4) = o2;
    } else {
        #pragma unroll
        for (int q = 0; q < 8; ++q)
            if (base + q < n) { offs[base + q] = off + s[q]; cursor[base + q] = off + s[q]; }
    }
}

__global__ void fill_kernel(const int* __restrict__ snd, const int* __restrict__ rcv,
                            int* cursor, int* __restrict__ csr, int E)
{
    int t = blockIdx.x * blockDim.x + threadIdx.x;
    if (t < E) {
        int r = rcv[t];
        int p = atomicAdd(&cursor[r], 1);
        csr[p] = snd[t];
    }
}

// ---------------- staging: coalesced rows (NW warps stage NW*16 rows) ---------------
template <int NW>
__device__ __forceinline__ void stage_rows_mma(
    const float4* __restrict__ X4, uint8_t* a_hi, uint8_t* a_lo,
    int row0, int n, int wid, int lane)
{
    #pragma unroll 4
    for (int rr = 0; rr < 16; ++rr) {
        int r = wid * 16 + rr;
        int i = row0 + r;
        float4 v = make_float4(0.f, 0.f, 0.f, 0.f);
        if (i < n) v = X4[(size_t)i * 32 + lane];
        __nv_bfloat162 h01 = __floats2bfloat162_rn(v.x, v.y);
        __nv_bfloat162 h23 = __floats2bfloat162_rn(v.z, v.w);
        float2 f01 = __bfloat1622float2(h01);
        float2 f23 = __bfloat1622float2(h23);
        __nv_bfloat162 l01 = __floats2bfloat162_rn(v.x - f01.x, v.y - f01.y);
        __nv_bfloat162 l23 = __floats2bfloat162_rn(v.z - f23.x, v.w - f23.y);
        uint32_t off = (uint32_t)r * PKB + lane * 8;
        *(uint2*)(a_hi + off) = make_uint2(bf2u(h01), bf2u(h23));
        *(uint2*)(a_lo + off) = make_uint2(bf2u(l01), bf2u(l23));
    }
}

// 8-rows-per-warp variant (512 threads staging only 128 rows).
__device__ __forceinline__ void stage_rows_half(
    const float4* __restrict__ X4, uint8_t* a_hi, uint8_t* a_lo,
    int row0, int n, int wid, int lane)
{
    #pragma unroll 4
    for (int rr = 0; rr < 8; ++rr) {
        int r = wid * 8 + rr;
        int i = row0 + r;
        float4 v = make_float4(0.f, 0.f, 0.f, 0.f);
        if (i < n) v = X4[(size_t)i * 32 + lane];
        __nv_bfloat162 h01 = __floats2bfloat162_rn(v.x, v.y);
        __nv_bfloat162 h23 = __floats2bfloat162_rn(v.z, v.w);
        float2 f01 = __bfloat1622float2(h01);
        float2 f23 = __bfloat1622float2(h23);
        __nv_bfloat162 l01 = __floats2bfloat162_rn(v.x - f01.x, v.y - f01.y);
        __nv_bfloat162 l23 = __floats2bfloat162_rn(v.z - f23.x, v.w - f23.y);
        uint32_t off = (uint32_t)r * PKB + lane * 8;
        *(uint2*)(a_hi + off) = make_uint2(bf2u(h01), bf2u(h23));
        *(uint2*)(a_lo + off) = make_uint2(bf2u(l01), bf2u(l23));
    }
}

// ---------------- staging: CSR gather, 8 threads/row, interleaved loads -------------
template <int NW, int ROWS>
__device__ __forceinline__ void stage_gather_mma(
    const float4* __restrict__ H4, const int* __restrict__ offs,
    const int* __restrict__ csr, uint8_t* a_hi, uint8_t* a_lo,
    int row0, int n, int wid, int lane)
{
    const int cseg = lane & 7;
    #pragma unroll
    for (int pass = 0; pass < ROWS / (NW * 4); ++pass) {
        int r = pass * (NW * 4) + wid * 4 + (lane >> 3);
        int i = row0 + r;
        float acc[16];
        #pragma unroll
        for (int q = 0; q < 16; ++q) acc[q] = 0.f;
        float scl = 1.f;
        if (i < n) {
            int beg = __ldg(&offs[i]), end = __ldg(&offs[i + 1]);
            if (beg < end) {
                const float4* p = H4 + (size_t)__ldg(&csr[beg]) * 32 + cseg;
                float4 c0 = __ldg(p), c1 = __ldg(p + 8), c2 = __ldg(p + 16), c3 = __ldg(p + 24);
                for (int e = beg + 1; e < end; ++e) {
                    const float4* np = H4 + (size_t)__ldg(&csr[e]) * 32 + cseg;
                    float4 n0 = __ldg(np), n1 = __ldg(np + 8),
                           n2 = __ldg(np + 16), n3 = __ldg(np + 24);
                    acc[0]  += c0.x; acc[1]  += c0.y; acc[2]  += c0.z; acc[3]  += c0.w;
                    acc[4]  += c1.x; acc[5]  += c1.y; acc[6]  += c1.z; acc[7]  += c1.w;
                    acc[8]  += c2.x; acc[9]  += c2.y; acc[10] += c2.z; acc[11] += c2.w;
                    acc[12] += c3.x; acc[13] += c3.y; acc[14] += c3.z; acc[15] += c3.w;
                    c0 = n0; c1 = n1; c2 = n2; c3 = n3;
                }
                acc[0]  += c0.x; acc[1]  += c0.y; acc[2]  += c0.z; acc[3]  += c0.w;
                acc[4]  += c1.x; acc[5]  += c1.y; acc[6]  += c1.z; acc[7]  += c1.w;
                acc[8]  += c2.x; acc[9]  += c2.y; acc[10] += c2.z; acc[11] += c2.w;
                acc[12] += c3.x; acc[13] += c3.y; acc[14] += c3.z; acc[15] += c3.w;
            }
            scl = rsqrtf(fmaxf((float)(end - beg), 1.f));
        }
        #pragma unroll
        for (int q = 0; q < 16; ++q) acc[q] *= scl;

        #pragma unroll
        for (int qq = 0; qq < 4; ++qq) {
            float x0 = acc[4 * qq], x1 = acc[4 * qq + 1];
            float x2 = acc[4 * qq + 2], x3 = acc[4 * qq + 3];
            __nv_bfloat162 h01 = __floats2bfloat162_rn(x0, x1);
            __nv_bfloat162 h23 = __floats2bfloat162_rn(x2, x3);
            float2 f01 = __bfloat1622float2(h01);
            float2 f23 = __bfloat1622float2(h23);
            __nv_bfloat162 l01 = __floats2bfloat162_rn(x0 - f01.x, x1 - f01.y);
            __nv_bfloat162 l23 = __floats2bfloat162_rn(x2 - f23.x, x3 - f23.y);
            uint32_t off = (uint32_t)r * PKB + (cseg + 8 * qq) * 8;
            *(uint2*)(a_hi + off) = make_uint2(bf2u(h01), bf2u(h23));
            *(uint2*)(a_lo + off) = make_uint2(bf2u(l01), bf2u(l23));
        }
    }
}

// ---------------- 3-term bf16 MMA, one K=128 block, m32 x (NF16*16) per warp ---------
template <int NF16>
__device__ __forceinline__ void mma_block_t(
    float acc[2][NF16 * 2][4], uint32_t aH, uint32_t aL, uint32_t bH, uint32_t bL)
{
    #pragma unroll
    for (int k16 = 0; k16 < 8; ++k16) {
        const uint32_t kb = k16 * 32;
        uint32_t ah0[4], ah1[4], al0[4], al1[4];
        ldsm4(ah0, aH + kb);
        ldsm4(ah1, aH + 16 * PKB + kb);
        ldsm4(al0, aL + kb);
        ldsm4(al1, aL + 16 * PKB + kb);
        #pragma unroll
        for (int nf16 = 0; nf16 < NF16; ++nf16) {
            uint32_t bh[4], bl[4];
            ldsm4(bh, bH + nf16 * 16 * PKB + kb);
            ldsm4(bl, bL + nf16 * 16 * PKB + kb);
            const int nf = nf16 * 2;
            mma_bf16(acc[0][nf],     ah0, bh[0], bh[1]);
            mma_bf16(acc[0][nf],     ah0, bl[0], bl[1]);
            mma_bf16(acc[0][nf],     al0, bh[0], bh[1]);
            mma_bf16(acc[0][nf + 1], ah0, bh[2], bh[3]);
            mma_bf16(acc[0][nf + 1], ah0, bl[2], bl[3]);
            mma_bf16(acc[0][nf + 1], al0, bh[2], bh[3]);
            mma_bf16(acc[1][nf],     ah1, bh[0], bh[1]);
            mma_bf16(acc[1][nf],     ah1, bl[0], bl[1]);
            mma_bf16(acc[1][nf],     al1, bh[0], bh[1]);
            mma_bf16(acc[1][nf + 1], ah1, bh[2], bh[3]);
            mma_bf16(acc[1][nf + 1], ah1, bl[2], bl[3]);
            mma_bf16(acc[1][nf + 1], al1, bh[2], bh[3]);
        }
    }
}

// ---------------- dense GC layer: 512 threads, 256-row tiles ------------------------
#define MMA_SMEM 213504
__global__ __launch_bounds__(512, 1) void mma_dense_kernel(
    const float4* __restrict__ X4, const float4* __restrict__ Hin,
    const int* __restrict__ offs, const int* __restrict__ csr,
    const uint8_t* __restrict__ whi, const uint8_t* __restrict__ wlo,
    const float* __restrict__ bias, const int* __restrict__ sdeg,
    float* __restrict__ Hout, int n, int tiles)
{
    extern __shared__ uint8_t sm[];
    uint8_t* a_hi = sm;
    uint8_t* a_lo = sm + 69632;
    float* bias_sm = (float*)(sm + 208896);
    float* red1    = (float*)(sm + 209408);
    float* red2    = (float*)(sm + 211456);

    const int tid = threadIdx.x, wid = tid >> 5, lane = tid & 31;
    const int sub  = wid >> 3;
    const int mrow = (wid & 3) * 32 + sub * 128;
    const int ch   = (wid >> 2) & 1;
    const int ncol = ch * 64;
    const int q2   = (lane & 3) * 2;

    for (int idx = tid; idx < 2176; idx += 512) {
        ((uint4*)(sm + 139264))[idx] = ((const uint4*)whi)[idx];
        ((uint4*)(sm + 174080))[idx] = ((const uint4*)wlo)[idx];
    }
    if (tid < 128) bias_sm[tid] = bias[tid];
    __syncthreads();

    float brg[16];
    #pragma unroll
    for (int nf = 0; nf < 8; ++nf) {
        brg[2 * nf]     = bias_sm[ncol + nf * 8 + q2];
        brg[2 * nf + 1] = bias_sm[ncol + nf * 8 + q2 + 1];
    }
    int rl[4];
    #pragma unroll
    for (int ri = 0; ri < 4; ++ri)
        rl[ri] = mrow + (ri >> 1) * 16 + (ri & 1) * 8 + (lane >> 2);

    const uint32_t smb  = smem_u32(sm);
    const uint32_t aoff = (lane & 15) * PKB + (lane >> 4) * 16;
    const uint32_t boff = ((lane >> 4) * 8 + (lane & 7)) * PKB + ((lane >> 3) & 1) * 16;
    const uint32_t aH = smb + mrow * PKB + aoff;
    const uint32_t aL = smb + 69632 + mrow * PKB + aoff;
    const uint32_t bH = smb + 139264 + ncol * PKB + boff;
    const uint32_t bL = smb + 174080 + ncol * PKB + boff;

    for (int t = blockIdx.x; t < tiles; t += gridDim.x) {
        const int row0 = t * 256;
        __syncthreads();
        if (csr) stage_gather_mma<16, 256>(Hin, offs, csr, a_hi, a_lo, row0, n, wid, lane);
        else     stage_rows_mma<16>(X4, a_hi, a_lo, row0, n, wid, lane);
        __syncthreads();

        float acc[2][8][4];
        #pragma unroll
        for (int a = 0; a < 2; ++a)
            #pragma unroll
            for (int b = 0; b < 8; ++b)
                #pragma unroll
                for (int c = 0; c < 4; ++c) acc[a][b][c] = 0.f;

        mma_block_t<4>(acc, aH, aL, bH, bL);

        float rmax[4];
        #pragma unroll
        for (int ri = 0; ri < 4; ++ri) {
            const int mt = ri >> 1, h8 = (ri & 1) * 2;
            float m = -3.4e38f;
            #pragma unroll
            for (int nf = 0; nf < 8; ++nf) {
                float x0 = fmaxf(acc[mt][nf][h8]     + brg[2 * nf],     0.f);
                float x1 = fmaxf(acc[mt][nf][h8 + 1] + brg[2 * nf + 1], 0.f);
                acc[mt][nf][h8] = x0; acc[mt][nf][h8 + 1] = x1;
                m = fmaxf(m, fmaxf(x0, x1));
            }
            m = fmaxf(m, __shfl_xor_sync(0xffffffffu, m, 1));
            m = fmaxf(m, __shfl_xor_sync(0xffffffffu, m, 2));
            rmax[ri] = m;
            red1[ch * 256 + rl[ri]] = m;
        }
        __syncthreads();
        #pragma unroll
        for (int ri = 0; ri < 4; ++ri) {
            const int mt = ri >> 1, h8 = (ri & 1) * 2;
            float m = fmaxf(rmax[ri], red1[(ch ^ 1) * 256 + rl[ri]]);
            float s = 0.f;
            #pragma unroll
            for (int nf = 0; nf < 8; ++nf) {
                float v0 = __expf(acc[mt][nf][h8] - m);
                float v1 = __expf(acc[mt][nf][h8 + 1] - m);
                acc[mt][nf][h8] = v0; acc[mt][nf][h8 + 1] = v1;
                s += v0 + v1;
            }
            s += __shfl_xor_sync(0xffffffffu, s, 1);
            s += __shfl_xor_sync(0xffffffffu, s, 2);
            red2[ch * 256 + rl[ri]] = s;
        }
        __syncthreads();
        #pragma unroll
        for (int ri = 0; ri < 4; ++ri) {
            const int mt = ri >> 1, h8 = (ri & 1) * 2;
            const int i = row0 + rl[ri];
            if (i >= n) continue;
            float s = red2[rl[ri]] + red2[256 + rl[ri]];
            float scl = rsqrtf(fmaxf((float)__ldg(&sdeg[i]), 1.f)) / s;
            float* op = Hout + (size_t)i * HID + ncol;
            #pragma unroll
            for (int nf = 0; nf < 8; ++nf)
                *(float2*)(op + nf * 8 + q2) =
                    make_float2(acc[mt][nf][h8] * scl, acc[mt][nf][h8 + 1] * scl);
        }
    }
}

// ---------------- final: 512 threads, m32xn32 warps, K=256 two-pass ------------------
#define FINAL_SMEM 209408
__global__ __launch_bounds__(512, 1) void mma_final_kernel(
    const float4* __restrict__ Hin, const int* __restrict__ offs,
    const int* __restrict__ csr, const float4* __restrict__ nodes4,
    const uint8_t* __restrict__ w0hi, const uint8_t* __restrict__ w0lo,
    const uint8_t* __restrict__ w1hi, const uint8_t* __restrict__ w1lo,
    const float* __restrict__ bmu, const float* __restrict__ bls,
    float* __restrict__ out, int n, int tiles)
{
    extern __shared__ uint8_t sm[];
    uint8_t* a_hi = sm;
    uint8_t* a_lo = sm + 34816;
    float* bias_sm = (float*)(sm + 208896);

    const int tid = threadIdx.x, wid = tid >> 5, lane = tid & 31;
    const int mrow = (wid & 3) * 32;
    const int nsub = (wid >> 2) & 1;
    const int ch   = wid >> 3;
    const int ncol = ch * 64 + nsub * 32;
    const int q2   = (lane & 3) * 2;

    for (int idx = tid; idx < 2176; idx += 512) {
        ((uint4*)(sm + 69632))[idx]  = ((const uint4*)w0hi)[idx];
        ((uint4*)(sm + 104448))[idx] = ((const uint4*)w0lo)[idx];
        ((uint4*)(sm + 139264))[idx] = ((const uint4*)w1hi)[idx];
        ((uint4*)(sm + 174080))[idx] = ((const uint4*)w1lo)[idx];
    }
    if (tid < 64) bias_sm[tid] = bmu[tid];
    else if (tid < 128) bias_sm[tid] = bls[tid - 64];
    __syncthreads();

    float brg[8];
    #pragma unroll
    for (int nf = 0; nf < 4; ++nf) {
        brg[2 * nf]     = bias_sm[ncol + nf * 8 + q2];
        brg[2 * nf + 1] = bias_sm[ncol + nf * 8 + q2 + 1];
    }
    int rl[4];
    #pragma unroll
    for (int ri = 0; ri < 4; ++ri)
        rl[ri] = mrow + (ri >> 1) * 16 + (ri & 1) * 8 + (lane >> 2);

    const uint32_t smb  = smem_u32(sm);
    const uint32_t aoff = (lane & 15) * PKB + (lane >> 4) * 16;
    const uint32_t boff = ((lane >> 4) * 8 + (lane & 7)) * PKB + ((lane >> 3) & 1) * 16;
    const uint32_t aH  = smb + mrow * PKB + aoff;
    const uint32_t aL  = smb + 34816 + mrow * PKB + aoff;
    const uint32_t b0H = smb + 69632 + ncol * PKB + boff;
    const uint32_t b0L = smb + 104448 + ncol * PKB + boff;
    const uint32_t b1H = smb + 139264 + ncol * PKB + boff;
    const uint32_t b1L = smb + 174080 + ncol * PKB + boff;

    const int cc0 = nsub * 32;

    for (int t = blockIdx.x; t < tiles; t += gridDim.x) {
        const int row0 = t * 128;

        float acc[2][4][4];
        #pragma unroll
        for (int a = 0; a < 2; ++a)
            #pragma unroll
            for (int b = 0; b < 4; ++b)
                #pragma unroll
                for (int c = 0; c < 4; ++c) acc[a][b][c] = 0.f;

        __syncthreads();
        stage_gather_mma<16, 128>(Hin, offs, csr, a_hi, a_lo, row0, n, wid, lane);
        __syncthreads();
        mma_block_t<2>(acc, aH, aL, b0H, b0L);

        __syncthreads();
        stage_rows_half(nodes4, a_hi, a_lo, row0, n, wid, lane);
        __syncthreads();
        mma_block_t<2>(acc, aH, aL, b1H, b1L);

        #pragma unroll
        for (int ri = 0; ri < 4; ++ri) {
            const int mt = ri >> 1, h8 = (ri & 1) * 2;
            const int i = row0 + rl[ri];
            if (i >= n) continue;
            float* op = out + (ch ? (size_t)n * ZDIM : 0) + (size_t)i * ZDIM + cc0;
            #pragma unroll
            for (int nf = 0; nf < 4; ++nf)
                *(float2*)(op + nf * 8 + q2) =
                    make_float2(acc[mt][nf][h8]     + brg[2 * nf],
                                acc[mt][nf][h8 + 1] + brg[2 * nf + 1]);
        }
    }
}

// ---------------- launch -------------------------------------------------------------
extern "C" void kernel_launch(void* const* d_in, const int* in_sizes, int n_in,
                              void* d_out, int out_size)
{
    const float* nodes = (const float*)d_in[0];
    const int*   snd   = (const int*)d_in[1];
    const int*   rcv   = (const int*)d_in[2];
    const float* W0    = (const float*)d_in[3];
    const float* b0    = (const float*)d_in[4];
    const float* W1    = (const float*)d_in[5];
    const float* b1    = (const float*)d_in[6];
    const float* Wmu   = (const float*)d_in[7];
    const float* bmu   = (const float*)d_in[8];
    const float* Wls   = (const float*)d_in[9];
    const float* bls   = (const float*)d_in[10];
    float* out = (float*)d_out;

    const int n = in_sizes[0] / FIN;
    const int E = in_sizes[1];

    float *h, *h2;
    int *sdeg, *rdeg, *offs, *cursor, *csr, *bsum;
    uint8_t *w0p, *w1p, *wfp;
    cudaGetSymbolAddress((void**)&h,      g_h);
    cudaGetSymbolAddress((void**)&h2,     g_h2);
    cudaGetSymbolAddress((void**)&sdeg,   g_sdeg);
    cudaGetSymbolAddress((void**)&rdeg,   g_rdeg);
    cudaGetSymbolAddress((void**)&offs,   g_offs);
    cudaGetSymbolAddress((void**)&cursor, g_cursor);
    cudaGetSymbolAddress((void**)&csr,    g_csr);
    cudaGetSymbolAddress((void**)&bsum,   g_bsum);
    cudaGetSymbolAddress((void**)&w0p,    g_w0p);
    cudaGetSymbolAddress((void**)&w1p,    g_w1p);
    cudaGetSymbolAddress((void**)&wfp,    g_wfp);

    cudaFuncSetAttribute(mma_dense_kernel, cudaFuncAttributeMaxDynamicSharedMemorySize, MMA_SMEM);
    cudaFuncSetAttribute(mma_final_kernel, cudaFuncAttributeMaxDynamicSharedMemorySize, FINAL_SMEM);

    const int tiles256 = (n + 255) / 256;
    const int tiles128 = (n + 127) / 128;
    const int IMG = 128 * PKB;
    const int pzBlocks = ((n > 65536 ? n : 65536) + 255) / 256;
    const int NB = (n + 2047) / 2048;

    // 0: fused prep + degree-zero
    prep_zero_kernel<<<pzBlocks, 256>>>(W0, W1, Wmu, Wls, sdeg, rdeg, n);
    // 1: degree count
    count_deg_kernel<<<(E + 255) / 256, 256>>>(snd, rcv, sdeg, rdeg, E);

    // 2-4: multi-block scan of rdeg -> offs/cursor
    scan_reduce_kernel<<<NB, 256>>>(rdeg, bsum, n);
    scan_bsums_kernel<<<1, 32>>>(bsum, NB, offs, n);
    scan_apply_kernel<<<NB, 256>>>(rdeg, bsum, offs, cursor, n);

    // 5: CSR fill
    fill_kernel<<<(E + 255) / 256, 256>>>(snd, rcv, cursor, csr, E);

    // 6: layer-1 dense (coalesced staging)
    mma_dense_kernel<<<148, 512, MMA_SMEM>>>(
        (const float4*)nodes, nullptr, nullptr, nullptr,
        w0p, w0p + IMG, b0, sdeg, h, n, tiles256);

    // 7: layer-2 dense (interleaved 8-thread/row gather) — reads h, writes h2
    mma_dense_kernel<<<148, 512, MMA_SMEM>>>(
        nullptr, (const float4*)h, offs, csr,
        w1p, w1p + IMG, b1, sdeg, h2, n, tiles256);

    // 8: final heads (gather + concat)
    mma_final_kernel<<<148, 512, FINAL_SMEM>>>(
        (const float4*)h2, offs, csr, (const float4*)nodes,
        wfp, wfp + IMG, wfp + 2 * IMG, wfp + 3 * IMG,
        bmu, bls, out, n, tiles128);
}